// round 9
// baseline (speedup 1.0000x reference)
#include <cuda_runtime.h>
#include <cuda_bf16.h>
#include <math.h>
#include <stdint.h>

#define BROWS 8192
#define DDIM  512
#define KDIM  4096
#define LSTEPS 16

#define GM 128
#define GN 256
#define NCB (KDIM / GN)        // 16 column blocks per rowblock
#define NROWBLK (BROWS / GM)   // 64
#define NCHUNKS 16             // d-chunks of 32 (hi+lo staged together)
#define GTHREADS 512
#define STAGES 3

#define ROWB 144                           // 128B data (64 hi + 64 lo) + 16 pad
#define ABYTES (GM * ROWB)                 // 18432
#define BBYTES (GN * ROWB)                 // 36864
#define STAGEB (ABYTES + BBYTES)           // 55296
#define SMEM_DYN (STAGES * STAGEB)         // 165888

// ---------------- device state ----------------
__device__ __align__(128) float g_resid[BROWS * DDIM];
__device__ __align__(128) __nv_bfloat16 g_Abf[BROWS * 1024];  // [row][0:512)=hi,[512:1024)=lo
__device__ __align__(128) __nv_bfloat16 g_Bbf[KDIM * 1024];
__device__ float g_rnorm[BROWS];
__device__ float g_tnorm[BROWS];
__device__ float g_pA[4 * NCB * BROWS];
__device__ int   g_pS[4 * NCB * BROWS];
__device__ int   g_cnt[NROWBLK];           // split-K semaphores (zero-init, reset each step)

// ---------------- helpers ----------------
__device__ __forceinline__ uint32_t smem_u32(const void* p) {
    uint32_t a;
    asm("{ .reg .u64 t; cvta.to.shared.u64 t, %1; cvt.u32.u64 %0, t; }" : "=r"(a) : "l"(p));
    return a;
}
__device__ __forceinline__ void cpasync16(uint32_t dst, const void* src) {
    asm volatile("cp.async.cg.shared.global [%0], [%1], 16;" :: "r"(dst), "l"(src));
}
#define CP_COMMIT() asm volatile("cp.async.commit_group;" ::: "memory")

__device__ __forceinline__ void mma_bf16(float* d, const uint32_t* a, const uint32_t* b) {
    asm volatile(
        "mma.sync.aligned.m16n8k16.row.col.f32.bf16.bf16.f32 "
        "{%0,%1,%2,%3}, {%4,%5,%6,%7}, {%8,%9}, {%0,%1,%2,%3};"
        : "+f"(d[0]), "+f"(d[1]), "+f"(d[2]), "+f"(d[3])
        : "r"(a[0]), "r"(a[1]), "r"(a[2]), "r"(a[3]), "r"(b[0]), "r"(b[1]));
}

__device__ __forceinline__ void split_bf(float v, __nv_bfloat16& h, __nv_bfloat16& l) {
    h = __float2bfloat16(v);
    l = __float2bfloat16(v - __bfloat162float(h));
}

// ---------------- prep: split inputs into bf16 hi/lo, norms ----------------
__global__ __launch_bounds__(256)
void lex_prep(const float* __restrict__ targets, const float* __restrict__ codebook) {
    const int tid = threadIdx.x;
    const int m = tid >> 2, q = tid & 3;
    if (blockIdx.x < 128) {
        int row = blockIdx.x * 64 + m;
        const float* src = targets + (size_t)row * DDIM + q * 128;
        __nv_bfloat16* dst = g_Abf + (size_t)row * 1024 + q * 128;
        float sum = 0.f;
        #pragma unroll 8
        for (int i = 0; i < 128; ++i) {
            float v = src[i];
            sum += v * v;
            split_bf(v, dst[i], dst[512 + i]);
        }
        sum += __shfl_xor_sync(0xffffffffu, sum, 1);
        sum += __shfl_xor_sync(0xffffffffu, sum, 2);
        if (q == 0) { float n = sqrtf(sum); g_rnorm[row] = n; g_tnorm[row] = n; }
    } else {
        int row = (blockIdx.x - 128) * 64 + m;
        const float* src = codebook + (size_t)row * DDIM + q * 128;
        __nv_bfloat16* dst = g_Bbf + (size_t)row * 1024 + q * 128;
        #pragma unroll 8
        for (int i = 0; i < 128; ++i) {
            split_bf(src[i], dst[i], dst[512 + i]);
        }
    }
}

// ---------------- fused GEMM + top-4 + (last block) merge/rescore/update ----------------
__global__ __launch_bounds__(GTHREADS, 1)
void lex_gemm(const float* __restrict__ targets, const float* __restrict__ codebook,
              float* __restrict__ out, int step, float decay) {
    extern __shared__ char dsm[];
    __shared__ float s_cabs[2][GM][17];
    __shared__ int   s_csig[2][GM][17];
    __shared__ int   s_last;
    __shared__ int   s_k[4][GM];
    __shared__ int   s_act[GM];
    __shared__ float s_coef[GM];
    __shared__ int   s_kidx[GM];

    const int tid = threadIdx.x;
    const int wid = tid >> 5;
    const int lane = tid & 31;
    const int tg = lane >> 2;      // 0..7
    const int tq = lane & 3;       // 0..3
    const int wm = wid >> 2;       // 0..3  (32-row group)
    const int wn = wid & 3;        // 0..3  (64-col group)
    const int rowblock = blockIdx.x >> 4;
    const int cb = blockIdx.x & 15;
    const int rowbase = rowblock * GM;
    const int colbase = cb * GN;
    const uint32_t sbase = smem_u32(dsm);
    const float* src = (step == 0) ? targets : g_resid;

    auto issue = [&](int c) {
        const int dbase = c * 32;
        const uint32_t base = sbase + (uint32_t)(c % STAGES) * STAGEB;
        #pragma unroll
        for (int i = 0; i < 2; ++i) {
            int idx = tid + i * GTHREADS;     // 0..1023
            int r = idx >> 3;
            int seg = (idx >> 2) & 1, c16 = idx & 3;
            cpasync16(base + (uint32_t)(r * ROWB + seg * 64 + c16 * 16),
                      g_Abf + (size_t)(rowbase + r) * 1024 + seg * 512 + dbase + c16 * 8);
        }
        #pragma unroll
        for (int i = 0; i < 4; ++i) {
            int idx = tid + i * GTHREADS;     // 0..2047
            int n = idx >> 3;
            int seg = (idx >> 2) & 1, c16 = idx & 3;
            cpasync16(base + ABYTES + (uint32_t)(n * ROWB + seg * 64 + c16 * 16),
                      g_Bbf + (size_t)(colbase + n) * 1024 + seg * 512 + dbase + c16 * 8);
        }
        CP_COMMIT();
    };

    float acc[2][8][4];
    #pragma unroll
    for (int i = 0; i < 2; ++i)
        #pragma unroll
        for (int j = 0; j < 8; ++j)
            #pragma unroll
            for (int r = 0; r < 4; ++r) acc[i][j][r] = 0.f;

    issue(0); issue(1);

    for (int c = 0; c < NCHUNKS; ++c) {
        asm volatile("cp.async.wait_group 1;" ::: "memory");
        __syncthreads();
        if (c + 2 < NCHUNKS) issue(c + 2);
        else CP_COMMIT();                       // keep group accounting uniform

        const char* As = dsm + (size_t)(c % STAGES) * STAGEB;
        const char* Bs = As + ABYTES;

        #pragma unroll
        for (int ks = 0; ks < 2; ++ks) {
            const int koff = ks * 32;           // 16 bf16 = 32 bytes within 64B seg
            uint32_t ah[2][4], al[2][4];
            #pragma unroll
            for (int i = 0; i < 2; ++i) {
                const char* p = As + (wm * 32 + i * 16 + tg) * ROWB + koff + tq * 4;
                ah[i][0] = *(const uint32_t*)(p);
                ah[i][1] = *(const uint32_t*)(p + 8 * ROWB);
                ah[i][2] = *(const uint32_t*)(p + 16);
                ah[i][3] = *(const uint32_t*)(p + 8 * ROWB + 16);
                al[i][0] = *(const uint32_t*)(p + 64);
                al[i][1] = *(const uint32_t*)(p + 8 * ROWB + 64);
                al[i][2] = *(const uint32_t*)(p + 80);
                al[i][3] = *(const uint32_t*)(p + 8 * ROWB + 80);
            }
            uint32_t bh[8][2], bl[8][2];
            #pragma unroll
            for (int j = 0; j < 8; ++j) {
                const char* p = Bs + (wn * 64 + j * 8 + tg) * ROWB + koff + tq * 4;
                bh[j][0] = *(const uint32_t*)(p);
                bh[j][1] = *(const uint32_t*)(p + 16);
                bl[j][0] = *(const uint32_t*)(p + 64);
                bl[j][1] = *(const uint32_t*)(p + 80);
            }
            #pragma unroll
            for (int i = 0; i < 2; ++i)
                #pragma unroll
                for (int j = 0; j < 8; ++j) {
                    mma_bf16(acc[i][j], ah[i], bh[j]);   // hi*hi
                    mma_bf16(acc[i][j], al[i], bh[j]);   // lo*hi
                    mma_bf16(acc[i][j], ah[i], bl[j]);   // hi*lo
                }
        }
    }

    // ---- per-thread top-2 candidates per row-slot ----
    #pragma unroll
    for (int i = 0; i < 2; ++i) {
        #pragma unroll
        for (int h = 0; h < 2; ++h) {
            float a1 = -1.f, a2 = -1.f;
            int s1 = 0, s2 = 0;
            #pragma unroll
            for (int j = 0; j < 8; ++j) {
                #pragma unroll
                for (int cc = 0; cc < 2; ++cc) {
                    float v = acc[i][j][h * 2 + cc];
                    float a = fabsf(v);
                    int k = colbase + wn * 64 + j * 8 + tq * 2 + cc;
                    int sg = (v >= 0.f) ? k : -(k + 1);
                    if (a > a1) { a2 = a1; s2 = s1; a1 = a; s1 = sg; }
                    else if (a > a2) { a2 = a; s2 = sg; }
                }
            }
            int rl = wm * 32 + i * 16 + tg + 8 * h;
            s_cabs[0][rl][wn * 4 + tq] = a1;
            s_csig[0][rl][wn * 4 + tq] = s1;
            s_cabs[1][rl][wn * 4 + tq] = a2;
            s_csig[1][rl][wn * 4 + tq] = s2;
        }
    }
    __syncthreads();

    // ---- per-row merge 32 -> top-4, publish candidates ----
    if (tid < GM) {
        float A_[4] = {-1.f, -1.f, -1.f, -1.f};
        int   S_[4] = {0, 0, 0, 0};
        #pragma unroll
        for (int t = 0; t < 16; ++t) {
            #pragma unroll
            for (int slot = 0; slot < 2; ++slot) {
                float a = s_cabs[slot][tid][t];
                int sg = s_csig[slot][tid][t];
                if (a > A_[3]) {
                    if (a > A_[0]) {
                        A_[3]=A_[2]; S_[3]=S_[2]; A_[2]=A_[1]; S_[2]=S_[1];
                        A_[1]=A_[0]; S_[1]=S_[0]; A_[0]=a; S_[0]=sg;
                    } else if (a > A_[1]) {
                        A_[3]=A_[2]; S_[3]=S_[2]; A_[2]=A_[1]; S_[2]=S_[1];
                        A_[1]=a; S_[1]=sg;
                    } else if (a > A_[2]) {
                        A_[3]=A_[2]; S_[3]=S_[2]; A_[2]=a; S_[2]=sg;
                    } else {
                        A_[3]=a; S_[3]=sg;
                    }
                }
            }
        }
        #pragma unroll
        for (int s = 0; s < 4; ++s) {
            g_pA[(cb * 4 + s) * BROWS + rowbase + tid] = A_[s];
            g_pS[(cb * 4 + s) * BROWS + rowbase + tid] = S_[s];
        }
        __threadfence();   // release candidate writes
    }
    __syncthreads();
    if (tid == 0) {
        int old = atomicAdd(&g_cnt[rowblock], 1);
        s_last = (old == NCB - 1) ? 1 : 0;
    }
    __syncthreads();
    if (!s_last) return;
    __threadfence();       // acquire other blocks' candidate writes

    // ======== last-arriving block: merge + exact rescore + residual update ========
    if (tid < GM) {
        int row = rowbase + tid;
        float A_[4] = {-1.f, -1.f, -1.f, -1.f};
        int   K_[4] = {0, 0, 0, 0};
        #pragma unroll
        for (int cbi = 0; cbi < NCB; ++cbi) {
            #pragma unroll
            for (int slot = 0; slot < 4; ++slot) {
                float a = g_pA[(cbi * 4 + slot) * BROWS + row];
                int sg = g_pS[(cbi * 4 + slot) * BROWS + row];
                int k = (sg >= 0) ? sg : (-sg - 1);
                if (a > A_[3]) {
                    if (a > A_[0]) {
                        A_[3]=A_[2]; K_[3]=K_[2]; A_[2]=A_[1]; K_[2]=K_[1];
                        A_[1]=A_[0]; K_[1]=K_[0]; A_[0]=a; K_[0]=k;
                    } else if (a > A_[1]) {
                        A_[3]=A_[2]; K_[3]=K_[2]; A_[2]=A_[1]; K_[2]=K_[1];
                        A_[1]=a; K_[1]=k;
                    } else if (a > A_[2]) {
                        A_[3]=A_[2]; K_[3]=K_[2]; A_[2]=a; K_[2]=k;
                    } else {
                        A_[3]=a; K_[3]=k;
                    }
                }
            }
        }
        #pragma unroll
        for (int s = 0; s < 4; ++s) s_k[s][tid] = K_[s];
        s_act[tid] = (g_rnorm[row] >= 0.01f) && (g_tnorm[row] >= 1e-8f);
    }
    __syncthreads();

    // exact fp32 rescore: thread -> (row = tid>>2, candidate = tid&3), full 512-dot
    {
        const int r = tid >> 2;
        const int cnd = tid & 3;
        int k = s_k[cnd][r];
        const float* rp = src + (size_t)(rowbase + r) * DDIM;
        const float* cp = codebook + (size_t)k * DDIM;
        float d = 0.f;
        #pragma unroll 4
        for (int i = 0; i < 128; ++i) {
            float4 r4 = *(const float4*)(rp + i * 4);
            float4 c4 = *(const float4*)(cp + i * 4);
            d += r4.x * c4.x + r4.y * c4.y + r4.z * c4.z + r4.w * c4.w;
        }
        float a = fabsf(d);
        #pragma unroll
        for (int off = 1; off <= 2; off <<= 1) {
            float a2 = __shfl_xor_sync(0xffffffffu, a, off);
            float d2 = __shfl_xor_sync(0xffffffffu, d, off);
            int   k2 = __shfl_xor_sync(0xffffffffu, k, off);
            if (a2 > a || (a2 == a && k2 < k)) { a = a2; d = d2; k = k2; }
        }
        if (cnd == 0) {
            int row = rowbase + r;
            int bS = (d >= 0.f) ? k : -(k + 1);
            bool active = s_act[r];
            s_coef[r] = active ? ((d >= 0.f) ? decay : -decay) : 0.f;
            s_kidx[r] = k;
            out[(size_t)row * LSTEPS + step] = active ? (float)bS : 0.f;
            out[(size_t)BROWS * LSTEPS + (size_t)row * LSTEPS + step] = active ? 1.f : 0.f;
        }
    }
    __syncthreads();

    // residual update + bf16 re-split + rnorm
    {
        const bool lastStep = (step == LSTEPS - 1);
        float* resout = out + 2 * (size_t)BROWS * LSTEPS;
        const int m = tid >> 2, q = tid & 3;
        const int row = rowbase + m;
        const float coef = s_coef[m];
        const int kk = s_kidx[m];
        const size_t base = (size_t)row * DDIM + q * 128;
        const size_t cbo = (size_t)kk * DDIM + q * 128;
        __nv_bfloat16* dst = g_Abf + (size_t)row * 1024 + q * 128;
        float sum = 0.f;
        #pragma unroll 8
        for (int i = 0; i < 32; ++i) {
            float4 r4 = *(const float4*)(src + base + i * 4);
            float4 c4 = *(const float4*)(codebook + cbo + i * 4);
            float4 o;
            o.x = r4.x - coef * c4.x;
            o.y = r4.y - coef * c4.y;
            o.z = r4.z - coef * c4.z;
            o.w = r4.w - coef * c4.w;
            sum += o.x * o.x + o.y * o.y + o.z * o.z + o.w * o.w;
            *(float4*)(g_resid + base + i * 4) = o;
            split_bf(o.x, dst[i * 4 + 0], dst[512 + i * 4 + 0]);
            split_bf(o.y, dst[i * 4 + 1], dst[512 + i * 4 + 1]);
            split_bf(o.z, dst[i * 4 + 2], dst[512 + i * 4 + 2]);
            split_bf(o.w, dst[i * 4 + 3], dst[512 + i * 4 + 3]);
            if (lastStep) *(float4*)(resout + base + i * 4) = o;
        }
        sum += __shfl_xor_sync(0xffffffffu, sum, 1);
        sum += __shfl_xor_sync(0xffffffffu, sum, 2);
        if (q == 0) g_rnorm[row] = sqrtf(sum);
    }
    __syncthreads();
    if (tid == 0) g_cnt[rowblock] = 0;   // reset for next step (kernel boundary orders this)
}

extern "C" void kernel_launch(void* const* d_in, const int* in_sizes, int n_in,
                              void* d_out, int out_size) {
    (void)n_in; (void)out_size;
    const float* targets;
    const float* codebook;
    if (in_sizes[0] == BROWS * DDIM) {
        targets  = (const float*)d_in[0];
        codebook = (const float*)d_in[1];
    } else {
        targets  = (const float*)d_in[1];
        codebook = (const float*)d_in[0];
    }
    cudaFuncSetAttribute(lex_gemm, cudaFuncAttributeMaxDynamicSharedMemorySize, SMEM_DYN);
    float* out = (float*)d_out;

    lex_prep<<<192, 256>>>(targets, codebook);
    for (int s = 0; s < LSTEPS; ++s) {
        float decay = powf(0.95f, (float)(s + 1));
        lex_gemm<<<NROWBLK * NCB, GTHREADS, SMEM_DYN>>>(targets, codebook, out, s, decay);
    }
}

// round 10
// speedup vs baseline: 1.3877x; 1.3877x over previous
#include <cuda_runtime.h>
#include <cuda_bf16.h>
#include <math.h>
#include <stdint.h>

#define BROWS 8192
#define DDIM  512
#define KDIM  4096
#define LSTEPS 16

#define GM 128
#define GN 256
#define NCB (KDIM / GN)        // 16 column blocks
#define NCHUNKS 16             // 16 d-chunks of 32 (hi+lo staged together)
#define GTHREADS 512
#define STAGES 3

#define ROWB 144                           // 128B data (64 hi + 64 lo) + 16 pad
#define ABYTES (GM * ROWB)                 // 18432
#define BBYTES (GN * ROWB)                 // 36864
#define STAGEB (ABYTES + BBYTES)           // 55296
#define SMEM_DYN (STAGES * STAGEB)         // 165888

// ---------------- device state ----------------
__device__ __align__(128) float g_resid[BROWS * DDIM];
__device__ __align__(128) __nv_bfloat16 g_Abf[BROWS * 1024];  // [row][0:512)=hi,[512:1024)=lo
__device__ __align__(128) __nv_bfloat16 g_Bbf[KDIM * 1024];
__device__ float g_rnorm[BROWS];
__device__ float g_tnorm[BROWS];
__device__ float g_pA[4 * NCB * BROWS];
__device__ int   g_pS[4 * NCB * BROWS];

// ---------------- helpers ----------------
__device__ __forceinline__ uint32_t smem_u32(const void* p) {
    uint32_t a;
    asm("{ .reg .u64 t; cvta.to.shared.u64 t, %1; cvt.u32.u64 %0, t; }" : "=r"(a) : "l"(p));
    return a;
}
__device__ __forceinline__ void cpasync16(uint32_t dst, const void* src) {
    asm volatile("cp.async.cg.shared.global [%0], [%1], 16;" :: "r"(dst), "l"(src));
}
#define CP_COMMIT() asm volatile("cp.async.commit_group;" ::: "memory")

__device__ __forceinline__ void mma_bf16(float* d, const uint32_t* a, const uint32_t* b) {
    asm volatile(
        "mma.sync.aligned.m16n8k16.row.col.f32.bf16.bf16.f32 "
        "{%0,%1,%2,%3}, {%4,%5,%6,%7}, {%8,%9}, {%0,%1,%2,%3};"
        : "+f"(d[0]), "+f"(d[1]), "+f"(d[2]), "+f"(d[3])
        : "r"(a[0]), "r"(a[1]), "r"(a[2]), "r"(a[3]), "r"(b[0]), "r"(b[1]));
}

__device__ __forceinline__ void split_bf(float v, __nv_bfloat16& h, __nv_bfloat16& l) {
    h = __float2bfloat16(v);
    l = __float2bfloat16(v - __bfloat162float(h));
}

// ---------------- prep: split inputs into bf16 hi/lo, norms ----------------
__global__ __launch_bounds__(256)
void lex_prep(const float* __restrict__ targets, const float* __restrict__ codebook) {
    const int tid = threadIdx.x;
    const int m = tid >> 2, q = tid & 3;
    if (blockIdx.x < 128) {
        int row = blockIdx.x * 64 + m;
        const float* src = targets + (size_t)row * DDIM + q * 128;
        __nv_bfloat16* dst = g_Abf + (size_t)row * 1024 + q * 128;
        float sum = 0.f;
        #pragma unroll 8
        for (int i = 0; i < 128; ++i) {
            float v = src[i];
            sum += v * v;
            split_bf(v, dst[i], dst[512 + i]);
        }
        sum += __shfl_xor_sync(0xffffffffu, sum, 1);
        sum += __shfl_xor_sync(0xffffffffu, sum, 2);
        if (q == 0) { float n = sqrtf(sum); g_rnorm[row] = n; g_tnorm[row] = n; }
    } else {
        int row = (blockIdx.x - 128) * 64 + m;
        const float* src = codebook + (size_t)row * DDIM + q * 128;
        __nv_bfloat16* dst = g_Bbf + (size_t)row * 1024 + q * 128;
        #pragma unroll 8
        for (int i = 0; i < 128; ++i) {
            split_bf(src[i], dst[i], dst[512 + i]);
        }
    }
}

// ---------------- GEMM (bf16 triple, fused hi/lo chunks) + top-4 ----------------
__global__ __launch_bounds__(GTHREADS, 1)
void lex_gemm() {
    extern __shared__ char dsm[];
    __shared__ float s_cabs[2][GM][17];
    __shared__ int   s_csig[2][GM][17];

    const int tid = threadIdx.x;
    const int wid = tid >> 5;      // 0..15
    const int lane = tid & 31;
    const int tg = lane >> 2;      // 0..7
    const int tq = lane & 3;       // 0..3
    const int wm = wid >> 2;       // 0..3  (32-row group)
    const int wn = wid & 3;        // 0..3  (64-col group)
    const int rowblock = blockIdx.x >> 4;
    const int cb = blockIdx.x & 15;
    const int rowbase = rowblock * GM;
    const int colbase = cb * GN;
    const uint32_t sbase = smem_u32(dsm);

    auto issue = [&](int c) {
        const int dbase = c * 32;
        const uint32_t base = sbase + (uint32_t)(c % STAGES) * STAGEB;
        #pragma unroll
        for (int i = 0; i < 2; ++i) {
            int idx = tid + i * GTHREADS;     // 0..1023
            int r = idx >> 3;
            int seg = (idx >> 2) & 1, c16 = idx & 3;
            cpasync16(base + (uint32_t)(r * ROWB + seg * 64 + c16 * 16),
                      g_Abf + (size_t)(rowbase + r) * 1024 + seg * 512 + dbase + c16 * 8);
        }
        #pragma unroll
        for (int i = 0; i < 4; ++i) {
            int idx = tid + i * GTHREADS;     // 0..2047
            int n = idx >> 3;
            int seg = (idx >> 2) & 1, c16 = idx & 3;
            cpasync16(base + ABYTES + (uint32_t)(n * ROWB + seg * 64 + c16 * 16),
                      g_Bbf + (size_t)(colbase + n) * 1024 + seg * 512 + dbase + c16 * 8);
        }
        CP_COMMIT();
    };

    float acc[2][8][4];
    #pragma unroll
    for (int i = 0; i < 2; ++i)
        #pragma unroll
        for (int j = 0; j < 8; ++j)
            #pragma unroll
            for (int r = 0; r < 4; ++r) acc[i][j][r] = 0.f;

    issue(0); issue(1);

    for (int c = 0; c < NCHUNKS; ++c) {
        asm volatile("cp.async.wait_group 1;" ::: "memory");
        __syncthreads();
        if (c + 2 < NCHUNKS) issue(c + 2);
        else CP_COMMIT();                       // keep group accounting uniform

        const char* As = dsm + (size_t)(c % STAGES) * STAGEB;
        const char* Bs = As + ABYTES;

        #pragma unroll
        for (int ks = 0; ks < 2; ++ks) {
            const int koff = ks * 32;           // 16 bf16 = 32 bytes within 64B seg
            uint32_t ah[2][4], al[2][4];
            #pragma unroll
            for (int i = 0; i < 2; ++i) {
                const char* p = As + (wm * 32 + i * 16 + tg) * ROWB + koff + tq * 4;
                ah[i][0] = *(const uint32_t*)(p);
                ah[i][1] = *(const uint32_t*)(p + 8 * ROWB);
                ah[i][2] = *(const uint32_t*)(p + 16);
                ah[i][3] = *(const uint32_t*)(p + 8 * ROWB + 16);
                al[i][0] = *(const uint32_t*)(p + 64);
                al[i][1] = *(const uint32_t*)(p + 8 * ROWB + 64);
                al[i][2] = *(const uint32_t*)(p + 80);
                al[i][3] = *(const uint32_t*)(p + 8 * ROWB + 80);
            }
            uint32_t bh[8][2], bl[8][2];
            #pragma unroll
            for (int j = 0; j < 8; ++j) {
                const char* p = Bs + (wn * 64 + j * 8 + tg) * ROWB + koff + tq * 4;
                bh[j][0] = *(const uint32_t*)(p);
                bh[j][1] = *(const uint32_t*)(p + 16);
                bl[j][0] = *(const uint32_t*)(p + 64);
                bl[j][1] = *(const uint32_t*)(p + 80);
            }
            // three pass-loops: same-acc reuse distance = 16 MMAs (no RAW chains)
            #pragma unroll
            for (int i = 0; i < 2; ++i)
                #pragma unroll
                for (int j = 0; j < 8; ++j)
                    mma_bf16(acc[i][j], ah[i], bh[j]);   // hi*hi
            #pragma unroll
            for (int i = 0; i < 2; ++i)
                #pragma unroll
                for (int j = 0; j < 8; ++j)
                    mma_bf16(acc[i][j], al[i], bh[j]);   // lo*hi
            #pragma unroll
            for (int i = 0; i < 2; ++i)
                #pragma unroll
                for (int j = 0; j < 8; ++j)
                    mma_bf16(acc[i][j], ah[i], bl[j]);   // hi*lo
        }
    }

    // ---- per-thread top-2 candidates per row-slot ----
    #pragma unroll
    for (int i = 0; i < 2; ++i) {
        #pragma unroll
        for (int h = 0; h < 2; ++h) {
            float a1 = -1.f, a2 = -1.f;
            int s1 = 0, s2 = 0;
            #pragma unroll
            for (int j = 0; j < 8; ++j) {
                #pragma unroll
                for (int cc = 0; cc < 2; ++cc) {
                    float v = acc[i][j][h * 2 + cc];
                    float a = fabsf(v);
                    int k = colbase + wn * 64 + j * 8 + tq * 2 + cc;
                    int sg = (v >= 0.f) ? k : -(k + 1);
                    if (a > a1) { a2 = a1; s2 = s1; a1 = a; s1 = sg; }
                    else if (a > a2) { a2 = a; s2 = sg; }
                }
            }
            int rl = wm * 32 + i * 16 + tg + 8 * h;
            s_cabs[0][rl][wn * 4 + tq] = a1;
            s_csig[0][rl][wn * 4 + tq] = s1;
            s_cabs[1][rl][wn * 4 + tq] = a2;
            s_csig[1][rl][wn * 4 + tq] = s2;
        }
    }
    __syncthreads();

    // ---- per-row merge 32 -> top-4, write candidates ----
    if (tid < GM) {
        float A_[4] = {-1.f, -1.f, -1.f, -1.f};
        int   S_[4] = {0, 0, 0, 0};
        #pragma unroll
        for (int t = 0; t < 16; ++t) {
            #pragma unroll
            for (int slot = 0; slot < 2; ++slot) {
                float a = s_cabs[slot][tid][t];
                int sg = s_csig[slot][tid][t];
                if (a > A_[3]) {
                    if (a > A_[0]) {
                        A_[3]=A_[2]; S_[3]=S_[2]; A_[2]=A_[1]; S_[2]=S_[1];
                        A_[1]=A_[0]; S_[1]=S_[0]; A_[0]=a; S_[0]=sg;
                    } else if (a > A_[1]) {
                        A_[3]=A_[2]; S_[3]=S_[2]; A_[2]=A_[1]; S_[2]=S_[1];
                        A_[1]=a; S_[1]=sg;
                    } else if (a > A_[2]) {
                        A_[3]=A_[2]; S_[3]=S_[2]; A_[2]=a; S_[2]=sg;
                    } else {
                        A_[3]=a; S_[3]=sg;
                    }
                }
            }
        }
        #pragma unroll
        for (int s = 0; s < 4; ++s) {
            g_pA[(cb * 4 + s) * BROWS + rowbase + tid] = A_[s];
            g_pS[(cb * 4 + s) * BROWS + rowbase + tid] = S_[s];
        }
    }
}

// ---------------- merge + exact fp32 rescore of top-4 + residual update ----------------
__global__ __launch_bounds__(256)
void lex_update(const float* __restrict__ targets, const float* __restrict__ codebook,
                float* __restrict__ out, int step, float decay) {
    __shared__ int   s_k[4][64];
    __shared__ int   s_act[64];
    __shared__ float s_coef[64];
    __shared__ int   s_kidx[64];
    const int tid = threadIdx.x;
    const int rowbase = blockIdx.x * 64;
    const float* src = (step == 0) ? targets : g_resid;

    if (tid < 64) {
        int row = rowbase + tid;
        float A_[4] = {-1.f, -1.f, -1.f, -1.f};
        int   K_[4] = {0, 0, 0, 0};
        #pragma unroll
        for (int cbi = 0; cbi < NCB; ++cbi) {
            #pragma unroll
            for (int slot = 0; slot < 4; ++slot) {
                float a = g_pA[(cbi * 4 + slot) * BROWS + row];
                int sg = g_pS[(cbi * 4 + slot) * BROWS + row];
                int k = (sg >= 0) ? sg : (-sg - 1);
                if (a > A_[3]) {
                    if (a > A_[0]) {
                        A_[3]=A_[2]; K_[3]=K_[2]; A_[2]=A_[1]; K_[2]=K_[1];
                        A_[1]=A_[0]; K_[1]=K_[0]; A_[0]=a; K_[0]=k;
                    } else if (a > A_[1]) {
                        A_[3]=A_[2]; K_[3]=K_[2]; A_[2]=A_[1]; K_[2]=K_[1];
                        A_[1]=a; K_[1]=k;
                    } else if (a > A_[2]) {
                        A_[3]=A_[2]; K_[3]=K_[2]; A_[2]=a; K_[2]=k;
                    } else {
                        A_[3]=a; K_[3]=k;
                    }
                }
            }
        }
        #pragma unroll
        for (int s = 0; s < 4; ++s) s_k[s][tid] = K_[s];
        s_act[tid] = (g_rnorm[row] >= 0.01f) && (g_tnorm[row] >= 1e-8f);
    }
    __syncthreads();

    const int m = tid >> 2, q = tid & 3;
    const int row = rowbase + m;
    const int k0 = s_k[0][m], k1 = s_k[1][m], k2 = s_k[2][m], k3 = s_k[3][m];
    {
        const float* rp = src + (size_t)row * DDIM + q * 128;
        const float* c0 = codebook + (size_t)k0 * DDIM + q * 128;
        const float* c1 = codebook + (size_t)k1 * DDIM + q * 128;
        const float* c2 = codebook + (size_t)k2 * DDIM + q * 128;
        const float* c3 = codebook + (size_t)k3 * DDIM + q * 128;
        float d0 = 0.f, d1 = 0.f, d2 = 0.f, d3 = 0.f;
        #pragma unroll 4
        for (int i = 0; i < 32; ++i) {
            float4 r4 = *(const float4*)(rp + i * 4);
            float4 v0 = *(const float4*)(c0 + i * 4);
            float4 v1 = *(const float4*)(c1 + i * 4);
            float4 v2 = *(const float4*)(c2 + i * 4);
            float4 v3 = *(const float4*)(c3 + i * 4);
            d0 += r4.x * v0.x + r4.y * v0.y + r4.z * v0.z + r4.w * v0.w;
            d1 += r4.x * v1.x + r4.y * v1.y + r4.z * v1.z + r4.w * v1.w;
            d2 += r4.x * v2.x + r4.y * v2.y + r4.z * v2.z + r4.w * v2.w;
            d3 += r4.x * v3.x + r4.y * v3.y + r4.z * v3.z + r4.w * v3.w;
        }
        d0 += __shfl_xor_sync(0xffffffffu, d0, 1); d0 += __shfl_xor_sync(0xffffffffu, d0, 2);
        d1 += __shfl_xor_sync(0xffffffffu, d1, 1); d1 += __shfl_xor_sync(0xffffffffu, d1, 2);
        d2 += __shfl_xor_sync(0xffffffffu, d2, 1); d2 += __shfl_xor_sync(0xffffffffu, d2, 2);
        d3 += __shfl_xor_sync(0xffffffffu, d3, 1); d3 += __shfl_xor_sync(0xffffffffu, d3, 2);
        if (q == 0) {
            float bD = d0; int bK = k0; float bA = fabsf(d0);
            float a1 = fabsf(d1);
            if (a1 > bA || (a1 == bA && k1 < bK)) { bA = a1; bD = d1; bK = k1; }
            float a2 = fabsf(d2);
            if (a2 > bA || (a2 == bA && k2 < bK)) { bA = a2; bD = d2; bK = k2; }
            float a3 = fabsf(d3);
            if (a3 > bA || (a3 == bA && k3 < bK)) { bA = a3; bD = d3; bK = k3; }
            int bS = (bD >= 0.f) ? bK : -(bK + 1);
            bool active = s_act[m];
            s_coef[m] = active ? ((bD >= 0.f) ? decay : -decay) : 0.f;
            s_kidx[m] = bK;
            out[(size_t)row * LSTEPS + step] = active ? (float)bS : 0.f;
            out[(size_t)BROWS * LSTEPS + (size_t)row * LSTEPS + step] = active ? 1.f : 0.f;
        }
    }
    __syncthreads();

    const bool last = (step == LSTEPS - 1);
    float* resout = out + 2 * (size_t)BROWS * LSTEPS;
    const float coef = s_coef[m];
    const int kk = s_kidx[m];
    const size_t base = (size_t)row * DDIM + q * 128;
    const size_t cbo = (size_t)kk * DDIM + q * 128;
    __nv_bfloat16* dst = g_Abf + (size_t)row * 1024 + q * 128;
    float sum = 0.f;
    #pragma unroll 8
    for (int i = 0; i < 32; ++i) {
        float4 r4 = *(const float4*)(src + base + i * 4);
        float4 c4 = *(const float4*)(codebook + cbo + i * 4);
        float4 o;
        o.x = r4.x - coef * c4.x;
        o.y = r4.y - coef * c4.y;
        o.z = r4.z - coef * c4.z;
        o.w = r4.w - coef * c4.w;
        sum += o.x * o.x + o.y * o.y + o.z * o.z + o.w * o.w;
        *(float4*)(g_resid + base + i * 4) = o;
        split_bf(o.x, dst[i * 4 + 0], dst[512 + i * 4 + 0]);
        split_bf(o.y, dst[i * 4 + 1], dst[512 + i * 4 + 1]);
        split_bf(o.z, dst[i * 4 + 2], dst[512 + i * 4 + 2]);
        split_bf(o.w, dst[i * 4 + 3], dst[512 + i * 4 + 3]);
        if (last) *(float4*)(resout + base + i * 4) = o;
    }
    sum += __shfl_xor_sync(0xffffffffu, sum, 1);
    sum += __shfl_xor_sync(0xffffffffu, sum, 2);
    if (q == 0) g_rnorm[row] = sqrtf(sum);
}

extern "C" void kernel_launch(void* const* d_in, const int* in_sizes, int n_in,
                              void* d_out, int out_size) {
    (void)n_in; (void)out_size;
    const float* targets;
    const float* codebook;
    if (in_sizes[0] == BROWS * DDIM) {
        targets  = (const float*)d_in[0];
        codebook = (const float*)d_in[1];
    } else {
        targets  = (const float*)d_in[1];
        codebook = (const float*)d_in[0];
    }
    cudaFuncSetAttribute(lex_gemm, cudaFuncAttributeMaxDynamicSharedMemorySize, SMEM_DYN);
    float* out = (float*)d_out;

    lex_prep<<<192, 256>>>(targets, codebook);
    for (int s = 0; s < LSTEPS; ++s) {
        float decay = powf(0.95f, (float)(s + 1));
        lex_gemm<<<(BROWS / GM) * NCB, GTHREADS, SMEM_DYN>>>();
        lex_update<<<BROWS / 64, 256>>>(targets, codebook, out, s, decay);
    }
}